// round 4
// baseline (speedup 1.0000x reference)
#include <cuda_runtime.h>
#include <cstdint>

// Degenerate conv (reference uses only x[:,0] and w[:,2]):
//   out(n,f,i,j) = bias[f] + sum_{a,b} w[f,2,a,b] * x[n,0,i+a,j+b]
//   x: (16,3,256,256) f32, w: (64,3,3,3) f32, b: (64,) f32
//   out: (16,64,254,254) f32
#define NB     16
#define F_OUT  64
#define F_HALF 32                 // filters per thread
#define Hh     256
#define Ww     256
#define HO     254
#define WO     254
#define IP     (HO / 2)           // 127 row-pairs (i even)
#define JQ4    63                 // 4-wide col tiles, j = 0..251
// main: 2x4 patches, 2 filter halves
#define N_MAIN (NB * IP * JQ4 * 2)   // 256032
// tail: 2x2 patch at j=252, 2 filter halves
#define N_TAIL (NB * IP * 2)         // 4064
#define N_TOT  (N_MAIN + N_TAIL)     // 260096 = 1016 * 256 exactly

typedef unsigned long long u64;

// packed f32x2 FMA (Blackwell): d = a * w + c on both lanes
static __device__ __forceinline__ u64 ffma2(u64 a, u64 w, u64 c) {
    u64 d;
    asm("fma.rn.f32x2 %0, %1, %2, %3;" : "=l"(d) : "l"(a), "l"(w), "l"(c));
    return d;
}

static __device__ __forceinline__ u64 pack2(float lo, float hi) {
    u64 d;
    asm("mov.b64 %0, {%1, %2};" : "=l"(d) : "f"(lo), "f"(hi));
    return d;
}

__global__ __launch_bounds__(256) void conv2dcq_kernel(
    const float* __restrict__ x,
    const float* __restrict__ w,
    const float* __restrict__ bias,
    float* __restrict__ out) {

    // Weights duplicated to (w,w) f32x2 in smem; bias likewise.
    __shared__ u64 sw[F_OUT * 9];
    __shared__ u64 sb[F_OUT];

    const int tid = threadIdx.x;
    for (int t = tid; t < F_OUT * 9; t += blockDim.x) {
        const float v = w[(t / 9) * 27 + 18 + (t % 9)];   // w[f, 2, a, b]
        sw[t] = pack2(v, v);
    }
    if (tid < F_OUT) {
        const float v = bias[tid];
        sb[tid] = pack2(v, v);
    }
    __syncthreads();

    const int idx = blockIdx.x * blockDim.x + tid;

    if (idx < N_MAIN) {
        // ---- main path: 2 rows x 4 cols, 32 filters per thread ----
        // filter half = slowest dim (keeps warps spatially coherent)
        const int half = N_MAIN / 2;                       // 128016
        const int sp = (idx < half) ? idx : (idx - half);
        const int f0 = (idx < half) ? 0 : F_HALF;

        const int jq = sp % JQ4;
        const int t2 = sp / JQ4;
        const int ip = t2 % IP;
        const int n  = t2 / IP;
        const int i  = ip * 2;        // even
        const int j  = jq * 4;        // multiple of 4

        const float* xb = x + (size_t)n * 3 * Hh * Ww + (size_t)i * Ww + j;

        // P[r][s] = (x[i+r][j+s], x[i+r][j+s+1]), r=0..3, s=0..4
        u64 P[4][5];
        #pragma unroll
        for (int r = 0; r < 4; r++) {
            const float4 lo = *reinterpret_cast<const float4*>(xb + (size_t)r * Ww);
            const float2 hi = *reinterpret_cast<const float2*>(xb + (size_t)r * Ww + 4);
            P[r][0] = pack2(lo.x, lo.y);
            P[r][1] = pack2(lo.y, lo.z);
            P[r][2] = pack2(lo.z, lo.w);
            P[r][3] = pack2(lo.w, hi.x);
            P[r][4] = pack2(hi.x, hi.y);
        }

        float* ob = out + (size_t)n * F_OUT * HO * WO
                        + (size_t)f0 * HO * WO
                        + (size_t)i * WO + j;

        #pragma unroll 2
        for (int f = f0; f < f0 + F_HALF; f++) {
            const u64 bb = sb[f];
            u64 a00 = bb, a01 = bb;   // row i,   cols j..j+1 / j+2..j+3
            u64 a10 = bb, a11 = bb;   // row i+1
            const u64* wf = &sw[f * 9];
            #pragma unroll
            for (int a = 0; a < 3; a++) {
                #pragma unroll
                for (int b = 0; b < 3; b++) {
                    const u64 wv = wf[a * 3 + b];    // LDS.64
                    a00 = ffma2(P[a][b],         wv, a00);
                    a01 = ffma2(P[a][b + 2],     wv, a01);
                    a10 = ffma2(P[a + 1][b],     wv, a10);
                    a11 = ffma2(P[a + 1][b + 2], wv, a11);
                }
            }
            // row i: base 16B-aligned (i even -> i*1016 = 2032*m; j mult of 4)
            reinterpret_cast<ulonglong2*>(ob)[0] = make_ulonglong2(a00, a01);
            // row i+1: +1016 B -> only 8B-aligned
            *reinterpret_cast<u64*>(ob + WO)     = a10;
            *reinterpret_cast<u64*>(ob + WO + 2) = a11;
            ob += (size_t)HO * WO;
        }
    } else {
        // ---- tail path: 2 rows x 2 cols at j = 252, 32 filters ----
        const int t0 = idx - N_MAIN;
        const int half = N_TAIL / 2;                       // 2032
        const int sp = (t0 < half) ? t0 : (t0 - half);
        const int f0 = (t0 < half) ? 0 : F_HALF;

        const int ip = sp % IP;
        const int n  = sp / IP;
        const int i  = ip * 2;
        const int j  = 252;

        const float* xb = x + (size_t)n * 3 * Hh * Ww + (size_t)i * Ww + j;

        u64 P[4][3];
        #pragma unroll
        for (int r = 0; r < 4; r++) {
            // 252*4 = 1008 B, 16B-aligned
            const float4 v = *reinterpret_cast<const float4*>(xb + (size_t)r * Ww);
            P[r][0] = pack2(v.x, v.y);
            P[r][1] = pack2(v.y, v.z);
            P[r][2] = pack2(v.z, v.w);
        }

        float* ob = out + (size_t)n * F_OUT * HO * WO
                        + (size_t)f0 * HO * WO
                        + (size_t)i * WO + j;

        #pragma unroll 4
        for (int f = f0; f < f0 + F_HALF; f++) {
            u64 a0 = sb[f];
            u64 a1 = a0;
            const u64* wf = &sw[f * 9];
            #pragma unroll
            for (int a = 0; a < 3; a++) {
                #pragma unroll
                for (int b = 0; b < 3; b++) {
                    const u64 wv = wf[a * 3 + b];
                    a0 = ffma2(P[a][b],     wv, a0);
                    a1 = ffma2(P[a + 1][b], wv, a1);
                }
            }
            *reinterpret_cast<u64*>(ob)      = a0;
            *reinterpret_cast<u64*>(ob + WO) = a1;
            ob += (size_t)HO * WO;
        }
    }
}

extern "C" void kernel_launch(void* const* d_in, const int* in_sizes, int n_in,
                              void* d_out, int out_size) {
    const float* x    = (const float*)d_in[0];
    const float* w    = (const float*)d_in[1];
    const float* bias = (const float*)d_in[2];
    float* out        = (float*)d_out;

    const int block = 256;
    const int grid  = N_TOT / block;   // 1016 exactly
    conv2dcq_kernel<<<grid, block>>>(x, w, bias, out);
}

// round 5
// speedup vs baseline: 1.4482x; 1.4482x over previous
#include <cuda_runtime.h>
#include <cstdint>

// Degenerate conv (reference uses only x[:,0] and w[:,2]):
//   out(n,f,i,j) = bias[f] + sum_{a,b} w[f,2,a,b] * x[n,0,i+a,j+b]
//   x: (16,3,256,256) f32, w: (64,3,3,3) f32, b: (64,) f32
//   out: (16,64,254,254) f32
//
// Structure: 2x2 output patch per thread (warp-dense STG.64 stores),
// filter dimension split 4 ways (16 filters per thread) for latency hiding.
#define NB     16
#define F_OUT  64
#define F_Q    16                 // filters per thread (4-way split)
#define Hh     256
#define Ww     256
#define HO     254
#define WO     254
#define IP     (HO / 2)           // 127 row-pairs (i even)
#define JP     (WO / 2)           // 127 col-pairs (j even)
#define N_SPATIAL (NB * IP * JP)  // 258064 spatial 2x2 patches
#define N_TOT     (N_SPATIAL * 4) // 1032256 threads (x4 filter quarters)

typedef unsigned long long u64;

// packed f32x2 FMA (Blackwell): d = a * w + c on both lanes
static __device__ __forceinline__ u64 ffma2(u64 a, u64 w, u64 c) {
    u64 d;
    asm("fma.rn.f32x2 %0, %1, %2, %3;" : "=l"(d) : "l"(a), "l"(w), "l"(c));
    return d;
}

static __device__ __forceinline__ u64 pack2(float lo, float hi) {
    u64 d;
    asm("mov.b64 %0, {%1, %2};" : "=l"(d) : "f"(lo), "f"(hi));
    return d;
}

__global__ __launch_bounds__(256) void conv2dcq_kernel(
    const float* __restrict__ x,
    const float* __restrict__ w,
    const float* __restrict__ bias,
    float* __restrict__ out) {

    // Per-filter packed block of 5 ulonglong2 (16B each):
    //   (bias,w0) (w1,w2) (w3,w4) (w5,w6) (w7,w8), each value duplicated (v,v).
    // 5 LDS.128 per filter instead of 10 LDS.64.
    __shared__ ulonglong2 swb[F_OUT * 5];

    const int tid = threadIdx.x;
    {
        u64* sp = reinterpret_cast<u64*>(swb);
        for (int t = tid; t < F_OUT * 10; t += blockDim.x) {
            const int f = t / 10;
            const int k = t % 10;
            const float v = (k == 0) ? bias[f] : w[f * 27 + 18 + (k - 1)];
            sp[t] = pack2(v, v);
        }
    }
    __syncthreads();

    const int idx = blockIdx.x * blockDim.x + tid;
    if (idx >= N_TOT) return;

    const int q  = idx / N_SPATIAL;       // filter quarter 0..3 (slowest dim)
    const int sp = idx - q * N_SPATIAL;
    const int f0 = q * F_Q;

    const int jp = sp % JP;
    const int t2 = sp / JP;
    const int ip = t2 % IP;
    const int n  = t2 / IP;
    const int i  = ip * 2;        // even
    const int j  = jp * 2;        // even

    // Input channel 0: 4 rows x 4 cols for a 2x2 output patch.
    const float* xb = x + (size_t)n * 3 * Hh * Ww + (size_t)i * Ww + j;

    // P[r][b] = (x[i+r][j+b], x[i+r][j+b+1]) packed f32x2
    u64 P[4][3];
    #pragma unroll
    for (int r = 0; r < 4; r++) {
        const float2 lo = *reinterpret_cast<const float2*>(xb + (size_t)r * Ww);
        const float2 hi = *reinterpret_cast<const float2*>(xb + (size_t)r * Ww + 2);
        P[r][0] = pack2(lo.x, lo.y);
        P[r][1] = pack2(lo.y, hi.x);
        P[r][2] = pack2(hi.x, hi.y);
    }

    float* ob = out + (size_t)n * F_OUT * HO * WO
                    + (size_t)f0 * HO * WO
                    + (size_t)i * WO + j;

    const ulonglong2* wq = &swb[f0 * 5];

    #pragma unroll 4
    for (int f = 0; f < F_Q; f++) {
        // (bias, w0)
        const ulonglong2 q0 = wq[0];
        u64 a0 = q0.x, a1 = q0.x;
        a0 = ffma2(P[0][0], q0.y, a0);  a1 = ffma2(P[1][0], q0.y, a1);
        // (w1, w2)
        const ulonglong2 q1 = wq[1];
        a0 = ffma2(P[0][1], q1.x, a0);  a1 = ffma2(P[1][1], q1.x, a1);
        a0 = ffma2(P[0][2], q1.y, a0);  a1 = ffma2(P[1][2], q1.y, a1);
        // (w3, w4)
        const ulonglong2 q2 = wq[2];
        a0 = ffma2(P[1][0], q2.x, a0);  a1 = ffma2(P[2][0], q2.x, a1);
        a0 = ffma2(P[1][1], q2.y, a0);  a1 = ffma2(P[2][1], q2.y, a1);
        // (w5, w6)
        const ulonglong2 q3 = wq[3];
        a0 = ffma2(P[1][2], q3.x, a0);  a1 = ffma2(P[2][2], q3.x, a1);
        a0 = ffma2(P[2][0], q3.y, a0);  a1 = ffma2(P[3][0], q3.y, a1);
        // (w7, w8)
        const ulonglong2 q4 = wq[4];
        a0 = ffma2(P[2][1], q4.x, a0);  a1 = ffma2(P[3][1], q4.x, a1);
        a0 = ffma2(P[2][2], q4.y, a0);  a1 = ffma2(P[3][2], q4.y, a1);

        // warp-dense stores: consecutive threads -> consecutive 8B, 256B/warp
        *reinterpret_cast<u64*>(ob)      = a0;
        *reinterpret_cast<u64*>(ob + WO) = a1;

        ob += (size_t)HO * WO;
        wq += 5;
    }
}

extern "C" void kernel_launch(void* const* d_in, const int* in_sizes, int n_in,
                              void* d_out, int out_size) {
    const float* x    = (const float*)d_in[0];
    const float* w    = (const float*)d_in[1];
    const float* bias = (const float*)d_in[2];
    float* out        = (float*)d_out;

    const int block = 256;
    const int grid  = (N_TOT + block - 1) / block;   // 4033
    conv2dcq_kernel<<<grid, block>>>(x, w, bias, out);
}